// round 15
// baseline (speedup 1.0000x reference)
#include <cuda_runtime.h>
#include <math.h>
#include <stdint.h>

// Problem constants (fixed shapes from reference setup_inputs)
#define BATCH 16
#define CIN   128
#define C2    256     // 2*CIN (cos plane + sin plane)
#define COUT  256
#define HW    56
#define PIX   (HW*HW) // 3136
#define TAPS  9

typedef unsigned long long u64;

// Scratch (device globals: allocation-free per harness rules)
// Input planes stored DUPLICATED (v,v) as float2 so cp.async can copy the
// packed-FMA broadcast operand directly. 103 MB.
__device__ __align__(16) float2 g_inp2[BATCH * C2 * PIX];
// Weights, R7 layout: [(c2*9+tap)*2+ri][cout]. 4.7 MB.
__device__ __align__(16) float g_w[C2 * TAPS * 2 * COUT];

// ---- Blackwell packed f32x2 ops (two independent IEEE fp32 lanes) ----
__device__ __forceinline__ u64 fma2(u64 a, u64 b, u64 c) {
    u64 d;
    asm("fma.rn.f32x2 %0, %1, %2, %3;" : "=l"(d) : "l"(a), "l"(b), "l"(c));
    return d;
}
__device__ __forceinline__ u64 add2(u64 a, u64 b) {
    u64 d;
    asm("add.rn.f32x2 %0, %1, %2;" : "=l"(d) : "l"(a), "l"(b));
    return d;
}
#define NEG2(x) ((x) ^ 0x8000000080000000ULL)

__device__ __forceinline__ void unpack2(u64 v, float& lo, float& hi) {
    asm("mov.b64 {%0, %1}, %2;" : "=f"(lo), "=f"(hi) : "l"(v));
}

// ---- cp.async helpers ----
__device__ __forceinline__ void cp16(uint32_t saddr, const void* g) {
    asm volatile("cp.async.cg.shared.global [%0], [%1], 16;"
                 :: "r"(saddr), "l"(g));
}
// 8B copy; when szr==0 the destination is zero-filled (src not read).
__device__ __forceinline__ void cp8z(uint32_t saddr, const void* g, int szr) {
    asm volatile("cp.async.ca.shared.global [%0], [%1], 8, %2;"
                 :: "r"(saddr), "l"(g), "r"(szr));
}
#define CP_COMMIT() asm volatile("cp.async.commit_group;" ::: "memory")
#define CP_WAIT0()  asm volatile("cp.async.wait_group 0;"  ::: "memory")

// ---------------------------------------------------------------------------
// Merged prep kernel (2 launches total).
//  i < N1: input planes  cos(x)->[0,128), sin(x)->[128,256), duplicated (v,v)
//  else  : trig weight products (R7 layout)
// probe/out layout: (1, Cin, Cout, 1, 1, 3, 3) -> flat ((cin*COUT+cout)*9+tap)
// ---------------------------------------------------------------------------
#define N1 (BATCH * CIN * PIX)
#define N2 (CIN * COUT * TAPS)

__global__ void prep_all(const float* __restrict__ x,
                         const float* __restrict__ probe,
                         const float* __restrict__ outang) {
    int i = blockIdx.x * blockDim.x + threadIdx.x;
    if (i < N1) {
        float v = x[i];
        int b   = i / (CIN * PIX);
        int rem = i % (CIN * PIX);
        int c   = rem / PIX;
        int p   = rem % PIX;
        float s, cs;
        sincosf(v, &s, &cs);
        g_inp2[(b * C2 + c) * PIX + p]        = make_float2(cs, cs);
        g_inp2[(b * C2 + c + CIN) * PIX + p]  = make_float2(s, s);
    } else {
        int j = i - N1;
        if (j >= N2) return;
        int cin  = j / (COUT * TAPS);
        int rem  = j % (COUT * TAPS);
        int cout = rem / TAPS;
        int tap  = rem % TAPS;
        float p = probe[j];
        float o = outang[j];
        float sp, cp, so, co;
        sincosf(p, &sp, &cp);
        sincosf(o, &so, &co);
        g_w[(( cin        * TAPS + tap) * 2 + 0) * COUT + cout] = cp * co;
        g_w[(( cin        * TAPS + tap) * 2 + 1) * COUT + cout] = cp * so;
        g_w[(((cin + CIN) * TAPS + tap) * 2 + 0) * COUT + cout] = sp * co;
        g_w[(((cin + CIN) * TAPS + tap) * 2 + 1) * COUT + cout] = sp * so;
    }
}

// ---------------------------------------------------------------------------
// Main conv kernel: R14 base (cp.async double-buffer, 128-reg cap,
// 2 blocks/SM) + LANE SWIZZLE ONLY:
//   ctl = (tid&7) | ((tid>>5)&1)<<3      -> 8 distinct cout-lanes per warp
//   pl  = ((tid>>3)&3) | ((tid>>6)&3)<<2 -> 4 distinct pixel-lanes per warp
// Weight LDS.128 per warp: 8 consecutive 16B slots = 128B = 1 wavefront
// (was 16 distinct = 256B = 2). Input LDS.128: 4 distinct = 64B = 1 wf.
// Global layouts, pipeline, and per-output arithmetic are IDENTICAL to R14
// (each output's op sequence unchanged; only its lane assignment moves).
//
// Grid: (4 cout-quarters of 64, 49 spatial tiles of 8x8, 16 batch).
// ---------------------------------------------------------------------------
#define CHUNK 4
#define W_FLOATS (CHUNK * TAPS * 2 * 64)    // 4608 floats (64-cout slice)
#define W_VEC4   (W_FLOATS / 4)             // 1152 float4
#define IN_PTS   (CHUNK * 10 * 10)          // 400 halo points (float2 (v,v))
#define NCHUNK   (C2 / CHUNK)               // 64

__global__ __launch_bounds__(256, 2)
void ring_conv(float* __restrict__ dout) {
    __shared__ __align__(16) float  s_w[2][W_FLOATS];
    __shared__ __align__(16) float2 s_in[2][IN_PTS];

    const int tid = threadIdx.x;
    const int ctl = (tid & 7) | (((tid >> 5) & 1) << 3);        // 0..15
    const int pl  = ((tid >> 3) & 3) | (((tid >> 6) & 3) << 2); // 0..15
    const int row  = pl >> 1;           // 0..7
    const int colb = (pl & 1) * 4;      // 0 or 4

    const int coutBase = blockIdx.x * 64;
    const int t     = blockIdx.y;
    const int tileY = (t / 7) * 8;
    const int tileX = (t % 7) * 8;
    const int b     = blockIdx.z;

    uint32_t s_in_base = (uint32_t)__cvta_generic_to_shared(&s_in[0][0]);
    uint32_t s_w_base  = (uint32_t)__cvta_generic_to_shared(&s_w[0][0]);
    const uint32_t IN_BUF_B = IN_PTS * 8;        // bytes per input buffer
    const uint32_t W_BUF_B  = W_FLOATS * 4;      // bytes per weight buffer

    // Issue all cp.async copies for one chunk into buffer `buf`.
    // (tid-linear indexing; unaffected by the compute-lane swizzle)
    auto issue_chunk = [&](int chunk, int buf) {
        const int ic0 = chunk * CHUNK;
        // inputs (8B, zero-filled when OOB)
#pragma unroll
        for (int it = 0; it < 2; ++it) {
            int i = tid + it * 256;
            if (i < IN_PTS) {
                int icl = i / 100;
                int p   = i % 100;
                int gy  = tileY + p / 10 - 1;
                int gx  = tileX + p % 10 - 1;
                bool ok = (unsigned)gy < (unsigned)HW && (unsigned)gx < (unsigned)HW;
                const float2* g = &g_inp2[(long)(b * C2 + ic0 + icl) * PIX
                                          + (ok ? gy * HW + gx : 0)];
                cp8z(s_in_base + buf * IN_BUF_B + i * 8, g, ok ? 8 : 0);
            }
        }
        // weights (16B)
#pragma unroll
        for (int it = 0; it < 5; ++it) {
            int i = tid + it * 256;          // float4 index
            if (i < W_VEC4) {
                int f   = i * 4;
                int icl = f / (TAPS * 2 * 64);
                int r   = (f % (TAPS * 2 * 64)) / 64;   // tap*2 + ri
                int col = f & 63;
                cp16(s_w_base + buf * W_BUF_B + i * 16,
                     &g_w[((ic0 + icl) * 18 + r) * COUT + coutBase + col]);
            }
        }
        CP_COMMIT();
    };

    // Prologue: start chunk 0 into buffer 0.
    issue_chunk(0, 0);

    // s = main sum, nc = NEGATED Kahan compensation
    u64 sRe[2][4], sIm[2][4];
    u64 ncRe[2][4], ncIm[2][4];
#pragma unroll
    for (int jp = 0; jp < 2; ++jp)
#pragma unroll
        for (int k = 0; k < 4; ++k) {
            sRe[jp][k] = 0ull; sIm[jp][k] = 0ull;
            ncRe[jp][k] = 0ull; ncIm[jp][k] = 0ull;
        }

    for (int chunk = 0; chunk < NCHUNK; ++chunk) {
        const int cur = chunk & 1;

        CP_WAIT0();        // this chunk's copies (only group in flight) done
        __syncthreads();   // visibility + everyone done reading other buffer

        if (chunk + 1 < NCHUNK)
            issue_chunk(chunk + 1, cur ^ 1);   // flies during compute below

        // ---- compute chunk partial (packed FMA, bit-identical order) ----
        u64 pRe[2][4], pIm[2][4];
#pragma unroll
        for (int jp = 0; jp < 2; ++jp)
#pragma unroll
            for (int k = 0; k < 4; ++k) { pRe[jp][k] = 0ull; pIm[jp][k] = 0ull; }

#pragma unroll
        for (int icl = 0; icl < CHUNK; ++icl) {
            const float2* in_base = &s_in[cur][icl * 100];
#pragma unroll
            for (int ky = 0; ky < 3; ++ky) {
                u64 vp[6];
                const ulonglong2* rp = reinterpret_cast<const ulonglong2*>(
                    &in_base[(row + ky) * 10 + colb]);
#pragma unroll
                for (int j = 0; j < 3; ++j) {
                    ulonglong2 q = rp[j];
                    vp[2 * j]     = q.x;
                    vp[2 * j + 1] = q.y;
                }
#pragma unroll
                for (int kx = 0; kx < 3; ++kx) {
                    const int tap = ky * 3 + kx;
                    const ulonglong2 wr = reinterpret_cast<const ulonglong2*>(
                        &s_w[cur][(icl * 18 + tap * 2 + 0) * 64])[ctl];
                    const ulonglong2 wi = reinterpret_cast<const ulonglong2*>(
                        &s_w[cur][(icl * 18 + tap * 2 + 1) * 64])[ctl];
                    u64 wra[2] = { wr.x, wr.y };
                    u64 wia[2] = { wi.x, wi.y };
#pragma unroll
                    for (int jp = 0; jp < 2; ++jp) {
#pragma unroll
                        for (int k = 0; k < 4; ++k) {
                            u64 xv = vp[k + kx];
                            pRe[jp][k] = fma2(wra[jp], xv, pRe[jp][k]);
                            pIm[jp][k] = fma2(wia[jp], xv, pIm[jp][k]);
                        }
                    }
                }
            }
        }

        // ---- Kahan merge (negated-compensation; exact IEEE negation) ----
#pragma unroll
        for (int jp = 0; jp < 2; ++jp) {
#pragma unroll
            for (int k = 0; k < 4; ++k) {
                {
                    u64 y1 = add2(pRe[jp][k], ncRe[jp][k]);
                    u64 tt = add2(sRe[jp][k], y1);
                    ncRe[jp][k] = add2(add2(sRe[jp][k], NEG2(tt)), y1);
                    sRe[jp][k] = tt;
                }
                {
                    u64 y1 = add2(pIm[jp][k], ncIm[jp][k]);
                    u64 tt = add2(sIm[jp][k], y1);
                    ncIm[jp][k] = add2(add2(sIm[jp][k], NEG2(tt)), y1);
                    sIm[jp][k] = tt;
                }
            }
        }
    }

    // ---- epilogue: angle = atan2(im, re) ----
    const int y = tileY + row;
#pragma unroll
    for (int jp = 0; jp < 2; ++jp) {
#pragma unroll
        for (int lane = 0; lane < 2; ++lane) {
            const int cout = coutBase + ctl * 4 + jp * 2 + lane;
            float* op = &dout[((b * COUT + cout) * HW + y) * HW + tileX + colb];
#pragma unroll
            for (int k = 0; k < 4; ++k) {
                float reLo, reHi, imLo, imHi;
                unpack2(sRe[jp][k], reLo, reHi);
                unpack2(sIm[jp][k], imLo, imHi);
                float re = lane ? reHi : reLo;
                float im = lane ? imHi : imLo;
                op[k] = atan2f(im, re);
            }
        }
    }
}

// ---------------------------------------------------------------------------
extern "C" void kernel_launch(void* const* d_in, const int* in_sizes, int n_in,
                              void* d_out, int out_size) {
    const float* x      = (const float*)d_in[0];
    const float* probe  = (const float*)d_in[1];
    const float* outang = (const float*)d_in[2];
    float* dout = (float*)d_out;

    (void)in_sizes; (void)n_in; (void)out_size;

    const int ntot = N1 + N2;
    prep_all<<<(ntot + 255) / 256, 256>>>(x, probe, outang);

    dim3 grid(4, 49, BATCH);
    ring_conv<<<grid, 256>>>(dout);
}